// round 1
// baseline (speedup 1.0000x reference)
#include <cuda_runtime.h>
#include <math.h>

// Problem constants
#define Bn   32
#define Cn   16
#define HWn  65536
#define TILES 32                         // tiles per batch
#define PIX_PER_BLOCK (HWn / TILES)      // 2048
#define THREADS 256
#define ITERS (PIX_PER_BLOCK / (THREADS * 4))   // 2 iterations of float4

// Scratch (allocation-free: __device__ globals)
// g_red[b][i]: i in [0,16)=totS, [16,32)=sum_cls0_S, [32,48)=totT, [48,64)=sum_cls0_T, 64=cnt_cls0
__device__ float  g_red[Bn][65];
__device__ float  g_meanS[Bn][2][Cn];
__device__ float  g_meanT[Bn][2][Cn];
__device__ float  g_nmS[Bn][2];
__device__ float  g_nmT[Bn][2];
__device__ int    g_is32;
__device__ double g_mse;

__device__ __forceinline__ float wred(float v) {
    v += __shfl_down_sync(0xFFFFFFFFu, v, 16);
    v += __shfl_down_sync(0xFFFFFFFFu, v, 8);
    v += __shfl_down_sync(0xFFFFFFFFu, v, 4);
    v += __shfl_down_sync(0xFFFFFFFFu, v, 2);
    v += __shfl_down_sync(0xFFFFFFFFu, v, 1);
    return v;
}

// ---------------------------------------------------------------------------
// Kernel 0: zero scratch + detect target dtype (int32 vs int64).
// For int64 targets with values in {0,1}, every odd 32-bit word is 0.
// For int32 targets, odd words are random class labels -> OR is nonzero
// with overwhelming certainty (prob of failure 2^-4096). Deterministic.
// ---------------------------------------------------------------------------
__global__ void zero_detect_kernel(const int* __restrict__ tw) {
    const int tid = threadIdx.x;
    float* red = &g_red[0][0];
    for (int i = tid; i < Bn * 65; i += THREADS) red[i] = 0.0f;
    if (tid == 0) g_mse = 0.0;

    int any = 0;
    for (int i = tid; i < 4096; i += THREADS) any |= tw[2 * i + 1];
    any = __syncthreads_or(any);
    if (tid == 0) g_is32 = (any != 0) ? 1 : 0;
}

// Load 4 consecutive pixel classes starting at pixel p (batch-local words base).
__device__ __forceinline__ void load_cls4(const int* __restrict__ twb, int p, int is32,
                                          int& c0, int& c1, int& c2, int& c3) {
    if (is32) {
        int4 v = *(const int4*)(twb + p);
        c0 = v.x; c1 = v.y; c2 = v.z; c3 = v.w;
    } else {
        int4 a = *(const int4*)(twb + 2 * p);
        int4 b = *(const int4*)(twb + 2 * p + 4);
        c0 = a.x; c1 = a.z; c2 = b.x; c3 = b.z;
    }
}

// ---------------------------------------------------------------------------
// Pass 1: per-(batch,class) sums of L2-normalized features + class-0 count.
// ---------------------------------------------------------------------------
__global__ void __launch_bounds__(THREADS) pass1_kernel(const float* __restrict__ S,
                                                        const float* __restrict__ T,
                                                        const int* __restrict__ TW) {
    const int b    = blockIdx.y;
    const int tile = blockIdx.x;
    const int tid  = threadIdx.x;
    const int is32 = g_is32;

    const float* Sb  = S + ((size_t)b << 20);
    const float* Tb  = T + ((size_t)b << 20);
    const int*   twb = TW + (is32 ? ((size_t)b << 16) : ((size_t)b << 17));

    float atS[Cn], a0S[Cn], atT[Cn], a0T[Cn];
#pragma unroll
    for (int c = 0; c < Cn; c++) { atS[c] = 0.f; a0S[c] = 0.f; atT[c] = 0.f; a0T[c] = 0.f; }
    float cnt0 = 0.f;

#pragma unroll
    for (int it = 0; it < ITERS; ++it) {
        const int p = tile * PIX_PER_BLOCK + it * (THREADS * 4) + tid * 4;

        int c0, c1, c2, c3;
        load_cls4(twb, p, is32, c0, c1, c2, c3);
        const float m0 = (c0 == 0) ? 1.f : 0.f;
        const float m1 = (c1 == 0) ? 1.f : 0.f;
        const float m2 = (c2 == 0) ? 1.f : 0.f;
        const float m3 = (c3 == 0) ? 1.f : 0.f;
        cnt0 += (m0 + m1) + (m2 + m3);

        // ---- S ----
        {
            float4 v[Cn];
#pragma unroll
            for (int c = 0; c < Cn; c++) v[c] = *(const float4*)(Sb + ((size_t)c << 16) + p);
            float n0 = 0.f, n1 = 0.f, n2 = 0.f, n3 = 0.f;
#pragma unroll
            for (int c = 0; c < Cn; c++) {
                n0 = fmaf(v[c].x, v[c].x, n0); n1 = fmaf(v[c].y, v[c].y, n1);
                n2 = fmaf(v[c].z, v[c].z, n2); n3 = fmaf(v[c].w, v[c].w, n3);
            }
            const float i0 = rsqrtf(fmaxf(n0, 1e-24f));
            const float i1 = rsqrtf(fmaxf(n1, 1e-24f));
            const float i2 = rsqrtf(fmaxf(n2, 1e-24f));
            const float i3 = rsqrtf(fmaxf(n3, 1e-24f));
#pragma unroll
            for (int c = 0; c < Cn; c++) {
                const float f0 = v[c].x * i0, f1 = v[c].y * i1;
                const float f2 = v[c].z * i2, f3 = v[c].w * i3;
                atS[c] += (f0 + f1) + (f2 + f3);
                a0S[c] += (m0 * f0 + m1 * f1) + (m2 * f2 + m3 * f3);
            }
        }
        // ---- T ----
        {
            float4 v[Cn];
#pragma unroll
            for (int c = 0; c < Cn; c++) v[c] = *(const float4*)(Tb + ((size_t)c << 16) + p);
            float n0 = 0.f, n1 = 0.f, n2 = 0.f, n3 = 0.f;
#pragma unroll
            for (int c = 0; c < Cn; c++) {
                n0 = fmaf(v[c].x, v[c].x, n0); n1 = fmaf(v[c].y, v[c].y, n1);
                n2 = fmaf(v[c].z, v[c].z, n2); n3 = fmaf(v[c].w, v[c].w, n3);
            }
            const float i0 = rsqrtf(fmaxf(n0, 1e-24f));
            const float i1 = rsqrtf(fmaxf(n1, 1e-24f));
            const float i2 = rsqrtf(fmaxf(n2, 1e-24f));
            const float i3 = rsqrtf(fmaxf(n3, 1e-24f));
#pragma unroll
            for (int c = 0; c < Cn; c++) {
                const float f0 = v[c].x * i0, f1 = v[c].y * i1;
                const float f2 = v[c].z * i2, f3 = v[c].w * i3;
                atT[c] += (f0 + f1) + (f2 + f3);
                a0T[c] += (m0 * f0 + m1 * f1) + (m2 * f2 + m3 * f3);
            }
        }
    }

    // Block reduction: warp shuffle -> smem -> one atomicAdd per slot.
    __shared__ float sred[THREADS / 32][65];
    const int lane = tid & 31, w = tid >> 5;
#pragma unroll
    for (int c = 0; c < Cn; c++) {
        atS[c] = wred(atS[c]); a0S[c] = wred(a0S[c]);
        atT[c] = wred(atT[c]); a0T[c] = wred(a0T[c]);
    }
    cnt0 = wred(cnt0);
    if (lane == 0) {
#pragma unroll
        for (int c = 0; c < Cn; c++) {
            sred[w][c]      = atS[c];
            sred[w][16 + c] = a0S[c];
            sred[w][32 + c] = atT[c];
            sred[w][48 + c] = a0T[c];
        }
        sred[w][64] = cnt0;
    }
    __syncthreads();
    if (tid < 65) {
        float s = 0.f;
#pragma unroll
        for (int ww = 0; ww < THREADS / 32; ww++) s += sred[ww][tid];
        atomicAdd(&g_red[b][tid], s);
    }
}

// ---------------------------------------------------------------------------
// Kernel 2: finalize class means and their norms. 64 threads = (b, cls).
// ---------------------------------------------------------------------------
__global__ void finalize_kernel() {
    const int tid = threadIdx.x;
    if (tid >= Bn * 2) return;
    const int b = tid >> 1, cls = tid & 1;
    const float cnt0 = g_red[b][64];
    const float cnt  = cls ? ((float)HWn - cnt0) : cnt0;
    const float inv  = 1.0f / (cnt + 1e-6f);
    float nm2S = 0.f, nm2T = 0.f;
#pragma unroll
    for (int c = 0; c < Cn; c++) {
        const float totS = g_red[b][c],      s0S = g_red[b][16 + c];
        const float totT = g_red[b][32 + c], s0T = g_red[b][48 + c];
        const float sS = cls ? (totS - s0S) : s0S;
        const float sT = cls ? (totT - s0T) : s0T;
        const float mS = sS * inv, mT = sT * inv;
        g_meanS[b][cls][c] = mS; nm2S = fmaf(mS, mS, nm2S);
        g_meanT[b][cls][c] = mT; nm2T = fmaf(mT, mT, nm2T);
    }
    g_nmS[b][cls] = sqrtf(nm2S);
    g_nmT[b][cls] = sqrtf(nm2T);
}

// ---------------------------------------------------------------------------
// Pass 3: per-pixel cosines vs own/other class mean, pcsim, MSE accumulation.
// ---------------------------------------------------------------------------
__global__ void __launch_bounds__(THREADS) pass3_kernel(const float* __restrict__ S,
                                                        const float* __restrict__ T,
                                                        const int* __restrict__ TW) {
    const int b    = blockIdx.y;
    const int tile = blockIdx.x;
    const int tid  = threadIdx.x;
    const int is32 = g_is32;

    __shared__ float smS[2][Cn], smT[2][Cn], snS[2], snT[2];
    if (tid < 32)       (&smS[0][0])[tid]      = (&g_meanS[b][0][0])[tid];
    else if (tid < 64)  (&smT[0][0])[tid - 32] = (&g_meanT[b][0][0])[tid - 32];
    else if (tid < 66)  snS[tid - 64] = g_nmS[b][tid - 64];
    else if (tid < 68)  snT[tid - 66] = g_nmT[b][tid - 66];
    __syncthreads();

    const float* Sb  = S + ((size_t)b << 20);
    const float* Tb  = T + ((size_t)b << 20);
    const int*   twb = TW + (is32 ? ((size_t)b << 16) : ((size_t)b << 17));

    const float nS0 = snS[0], nS1 = snS[1], nT0 = snT[0], nT1 = snT[1];

    float acc = 0.f;
#pragma unroll
    for (int it = 0; it < ITERS; ++it) {
        const int p = tile * PIX_PER_BLOCK + it * (THREADS * 4) + tid * 4;

        int c0, c1, c2, c3;
        load_cls4(twb, p, is32, c0, c1, c2, c3);
        const float s0 = (c0 == 0) ? 1.f : -1.f;
        const float s1 = (c1 == 0) ? 1.f : -1.f;
        const float s2 = (c2 == 0) ? 1.f : -1.f;
        const float s3 = (c3 == 0) ? 1.f : -1.f;

        float pcS0, pcS1, pcS2, pcS3;
        // ---- S ----
        {
            float4 v[Cn];
#pragma unroll
            for (int c = 0; c < Cn; c++) v[c] = *(const float4*)(Sb + ((size_t)c << 16) + p);
            float n0 = 0.f, n1 = 0.f, n2 = 0.f, n3 = 0.f;
            float dA0 = 0.f, dB0 = 0.f, dA1 = 0.f, dB1 = 0.f;
            float dA2 = 0.f, dB2 = 0.f, dA3 = 0.f, dB3 = 0.f;
#pragma unroll
            for (int c = 0; c < Cn; c++) {
                const float mA = smS[0][c], mB = smS[1][c];
                n0 = fmaf(v[c].x, v[c].x, n0); n1 = fmaf(v[c].y, v[c].y, n1);
                n2 = fmaf(v[c].z, v[c].z, n2); n3 = fmaf(v[c].w, v[c].w, n3);
                dA0 = fmaf(v[c].x, mA, dA0); dB0 = fmaf(v[c].x, mB, dB0);
                dA1 = fmaf(v[c].y, mA, dA1); dB1 = fmaf(v[c].y, mB, dB1);
                dA2 = fmaf(v[c].z, mA, dA2); dB2 = fmaf(v[c].z, mB, dB2);
                dA3 = fmaf(v[c].w, mA, dA3); dB3 = fmaf(v[c].w, mB, dB3);
            }
            const float i0 = rsqrtf(fmaxf(n0, 1e-24f)), i1 = rsqrtf(fmaxf(n1, 1e-24f));
            const float i2 = rsqrtf(fmaxf(n2, 1e-24f)), i3 = rsqrtf(fmaxf(n3, 1e-24f));
            const float f0 = sqrtf(n0) * i0, f1 = sqrtf(n1) * i1;   // ||feat|| (≈1)
            const float f2 = sqrtf(n2) * i2, f3 = sqrtf(n3) * i3;
            const float cd0 = (dA0 * i0) / fmaxf(f0 * nS0, 1e-8f) - (dB0 * i0) / fmaxf(f0 * nS1, 1e-8f);
            const float cd1 = (dA1 * i1) / fmaxf(f1 * nS0, 1e-8f) - (dB1 * i1) / fmaxf(f1 * nS1, 1e-8f);
            const float cd2 = (dA2 * i2) / fmaxf(f2 * nS0, 1e-8f) - (dB2 * i2) / fmaxf(f2 * nS1, 1e-8f);
            const float cd3 = (dA3 * i3) / fmaxf(f3 * nS0, 1e-8f) - (dB3 * i3) / fmaxf(f3 * nS1, 1e-8f);
            pcS0 = expf(s0 * cd0); pcS1 = expf(s1 * cd1);
            pcS2 = expf(s2 * cd2); pcS3 = expf(s3 * cd3);
        }
        // ---- T ----
        {
            float4 v[Cn];
#pragma unroll
            for (int c = 0; c < Cn; c++) v[c] = *(const float4*)(Tb + ((size_t)c << 16) + p);
            float n0 = 0.f, n1 = 0.f, n2 = 0.f, n3 = 0.f;
            float dA0 = 0.f, dB0 = 0.f, dA1 = 0.f, dB1 = 0.f;
            float dA2 = 0.f, dB2 = 0.f, dA3 = 0.f, dB3 = 0.f;
#pragma unroll
            for (int c = 0; c < Cn; c++) {
                const float mA = smT[0][c], mB = smT[1][c];
                n0 = fmaf(v[c].x, v[c].x, n0); n1 = fmaf(v[c].y, v[c].y, n1);
                n2 = fmaf(v[c].z, v[c].z, n2); n3 = fmaf(v[c].w, v[c].w, n3);
                dA0 = fmaf(v[c].x, mA, dA0); dB0 = fmaf(v[c].x, mB, dB0);
                dA1 = fmaf(v[c].y, mA, dA1); dB1 = fmaf(v[c].y, mB, dB1);
                dA2 = fmaf(v[c].z, mA, dA2); dB2 = fmaf(v[c].z, mB, dB2);
                dA3 = fmaf(v[c].w, mA, dA3); dB3 = fmaf(v[c].w, mB, dB3);
            }
            const float i0 = rsqrtf(fmaxf(n0, 1e-24f)), i1 = rsqrtf(fmaxf(n1, 1e-24f));
            const float i2 = rsqrtf(fmaxf(n2, 1e-24f)), i3 = rsqrtf(fmaxf(n3, 1e-24f));
            const float f0 = sqrtf(n0) * i0, f1 = sqrtf(n1) * i1;
            const float f2 = sqrtf(n2) * i2, f3 = sqrtf(n3) * i3;
            const float cd0 = (dA0 * i0) / fmaxf(f0 * nT0, 1e-8f) - (dB0 * i0) / fmaxf(f0 * nT1, 1e-8f);
            const float cd1 = (dA1 * i1) / fmaxf(f1 * nT0, 1e-8f) - (dB1 * i1) / fmaxf(f1 * nT1, 1e-8f);
            const float cd2 = (dA2 * i2) / fmaxf(f2 * nT0, 1e-8f) - (dB2 * i2) / fmaxf(f2 * nT1, 1e-8f);
            const float cd3 = (dA3 * i3) / fmaxf(f3 * nT0, 1e-8f) - (dB3 * i3) / fmaxf(f3 * nT1, 1e-8f);
            const float d0 = pcS0 - expf(s0 * cd0);
            const float d1 = pcS1 - expf(s1 * cd1);
            const float d2 = pcS2 - expf(s2 * cd2);
            const float d3 = pcS3 - expf(s3 * cd3);
            acc += (fmaf(d0, d0, d1 * d1)) + (fmaf(d2, d2, d3 * d3));
        }
    }

    // Block reduction of MSE partial
    __shared__ float smse[THREADS / 32];
    acc = wred(acc);
    const int lane = tid & 31, w = tid >> 5;
    if (lane == 0) smse[w] = acc;
    __syncthreads();
    if (tid == 0) {
        float s = 0.f;
#pragma unroll
        for (int ww = 0; ww < THREADS / 32; ww++) s += smse[ww];
        atomicAdd(&g_mse, (double)s);
    }
}

__global__ void writeout_kernel(float* out) {
    out[0] = (float)(g_mse * (1.0 / ((double)Bn * (double)HWn)));
}

extern "C" void kernel_launch(void* const* d_in, const int* in_sizes, int n_in,
                              void* d_out, int out_size) {
    const float* S  = (const float*)d_in[0];
    const float* T  = (const float*)d_in[1];
    const int*   TW = (const int*)d_in[2];   // target words (int32 or int64; sniffed)
    float* out = (float*)d_out;

    zero_detect_kernel<<<1, THREADS>>>(TW);
    dim3 grid(TILES, Bn);
    pass1_kernel<<<grid, THREADS>>>(S, T, TW);
    finalize_kernel<<<1, 64>>>();
    pass3_kernel<<<grid, THREADS>>>(S, T, TW);
    writeout_kernel<<<1, 1>>>(out);
}

// round 2
// speedup vs baseline: 1.0576x; 1.0576x over previous
#include <cuda_runtime.h>
#include <math.h>

// Problem constants
#define Bn   32
#define Cn   16
#define HWn  65536
#define TILES 32                          // tiles per batch
#define PIX_PER_BLOCK (HWn / TILES)       // 2048
#define THREADS 256

// pass1: 2 pixels/thread -> 4 iters; pass3: 4 pixels/thread -> 2 iters
#define ITERS1 (PIX_PER_BLOCK / (THREADS * 2))
#define ITERS3 (PIX_PER_BLOCK / (THREADS * 4))

// Scratch (allocation-free: __device__ globals)
// g_red[b][i]: [0,16)=totS, [16,32)=sum_cls0_S, [32,48)=totT, [48,64)=sum_cls0_T, 64=cnt_cls0
__device__ float  g_red[Bn][65];
__device__ float  g_meanS[Bn][2][Cn];
__device__ float  g_meanT[Bn][2][Cn];
__device__ float  g_nmS[Bn][2];
__device__ float  g_nmT[Bn][2];
__device__ int    g_is32;
__device__ double g_mse;

__device__ __forceinline__ float wred(float v) {
    v += __shfl_down_sync(0xFFFFFFFFu, v, 16);
    v += __shfl_down_sync(0xFFFFFFFFu, v, 8);
    v += __shfl_down_sync(0xFFFFFFFFu, v, 4);
    v += __shfl_down_sync(0xFFFFFFFFu, v, 2);
    v += __shfl_down_sync(0xFFFFFFFFu, v, 1);
    return v;
}

// ---------------------------------------------------------------------------
// Kernel 0: zero scratch + detect target dtype (int32 vs int64).
// int64 targets with values in {0,1}: every odd 32-bit word is 0.
// ---------------------------------------------------------------------------
__global__ void zero_detect_kernel(const int* __restrict__ tw) {
    const int tid = threadIdx.x;
    float* red = &g_red[0][0];
    for (int i = tid; i < Bn * 65; i += THREADS) red[i] = 0.0f;
    if (tid == 0) g_mse = 0.0;

    int any = 0;
    for (int i = tid; i < 4096; i += THREADS) any |= tw[2 * i + 1];
    any = __syncthreads_or(any);
    if (tid == 0) g_is32 = (any != 0) ? 1 : 0;
}

__device__ __forceinline__ void load_cls2(const int* __restrict__ twb, int p, int is32,
                                          int& c0, int& c1) {
    if (is32) {
        int2 v = *(const int2*)(twb + p);
        c0 = v.x; c1 = v.y;
    } else {
        int4 a = *(const int4*)(twb + 2 * p);
        c0 = a.x; c1 = a.z;
    }
}

__device__ __forceinline__ void load_cls4(const int* __restrict__ twb, int p, int is32,
                                          int& c0, int& c1, int& c2, int& c3) {
    if (is32) {
        int4 v = *(const int4*)(twb + p);
        c0 = v.x; c1 = v.y; c2 = v.z; c3 = v.w;
    } else {
        int4 a = *(const int4*)(twb + 2 * p);
        int4 b = *(const int4*)(twb + 2 * p + 4);
        c0 = a.x; c1 = a.z; c2 = b.x; c3 = b.z;
    }
}

// ---------------------------------------------------------------------------
// Pass 1 (one tensor): per-(batch,class) sums of L2-normalized features.
// 2 pixels/thread, float2 loads -> tile held in 32 regs, accumulators 32 regs.
// ---------------------------------------------------------------------------
__global__ void __launch_bounds__(THREADS, 3)
pass1_kernel(const float* __restrict__ X, const int* __restrict__ TW,
             int slotTot, int slotC0, int doCnt) {
    const int b    = blockIdx.y;
    const int tile = blockIdx.x;
    const int tid  = threadIdx.x;
    const int is32 = g_is32;

    const float* Xb  = X + ((size_t)b << 20);
    const int*   twb = TW + (is32 ? ((size_t)b << 16) : ((size_t)b << 17));

    float at[Cn], a0[Cn];
#pragma unroll
    for (int c = 0; c < Cn; c++) { at[c] = 0.f; a0[c] = 0.f; }
    float cnt = 0.f;

    for (int it = 0; it < ITERS1; ++it) {
        const int p = tile * PIX_PER_BLOCK + it * (THREADS * 2) + tid * 2;

        int c0, c1;
        load_cls2(twb, p, is32, c0, c1);
        const float m0 = (c0 == 0) ? 1.f : 0.f;
        const float m1 = (c1 == 0) ? 1.f : 0.f;
        cnt += m0 + m1;

        float2 v[Cn];
#pragma unroll
        for (int c = 0; c < Cn; c++) v[c] = *(const float2*)(Xb + ((size_t)c << 16) + p);

        float n0 = 0.f, n1 = 0.f;
#pragma unroll
        for (int c = 0; c < Cn; c++) {
            n0 = fmaf(v[c].x, v[c].x, n0);
            n1 = fmaf(v[c].y, v[c].y, n1);
        }
        const float i0 = rsqrtf(fmaxf(n0, 1e-24f));
        const float i1 = rsqrtf(fmaxf(n1, 1e-24f));

#pragma unroll
        for (int c = 0; c < Cn; c++) {
            const float f0 = v[c].x * i0;
            const float f1 = v[c].y * i1;
            at[c] += f0 + f1;
            a0[c] += fmaf(m0, f0, m1 * f1);
        }
    }

    __shared__ float sred[THREADS / 32][33];
    const int lane = tid & 31, w = tid >> 5;
#pragma unroll
    for (int c = 0; c < Cn; c++) { at[c] = wred(at[c]); a0[c] = wred(a0[c]); }
    cnt = wred(cnt);
    if (lane == 0) {
#pragma unroll
        for (int c = 0; c < Cn; c++) { sred[w][c] = at[c]; sred[w][16 + c] = a0[c]; }
        sred[w][32] = cnt;
    }
    __syncthreads();
    if (tid < 33) {
        float s = 0.f;
#pragma unroll
        for (int ww = 0; ww < THREADS / 32; ww++) s += sred[ww][tid];
        if (tid < 16)       atomicAdd(&g_red[b][slotTot + tid], s);
        else if (tid < 32)  atomicAdd(&g_red[b][slotC0 + tid - 16], s);
        else if (doCnt)     atomicAdd(&g_red[b][64], s);
    }
}

// ---------------------------------------------------------------------------
// Kernel 2: finalize class means and their norms. 64 threads = (b, cls).
// ---------------------------------------------------------------------------
__global__ void finalize_kernel() {
    const int tid = threadIdx.x;
    if (tid >= Bn * 2) return;
    const int b = tid >> 1, cls = tid & 1;
    const float cnt0 = g_red[b][64];
    const float cnt  = cls ? ((float)HWn - cnt0) : cnt0;
    const float inv  = 1.0f / (cnt + 1e-6f);
    float nm2S = 0.f, nm2T = 0.f;
#pragma unroll
    for (int c = 0; c < Cn; c++) {
        const float totS = g_red[b][c],      s0S = g_red[b][16 + c];
        const float totT = g_red[b][32 + c], s0T = g_red[b][48 + c];
        const float sS = cls ? (totS - s0S) : s0S;
        const float sT = cls ? (totT - s0T) : s0T;
        const float mS = sS * inv, mT = sT * inv;
        g_meanS[b][cls][c] = mS; nm2S = fmaf(mS, mS, nm2S);
        g_meanT[b][cls][c] = mT; nm2T = fmaf(mT, mT, nm2T);
    }
    g_nmS[b][cls] = sqrtf(nm2S);
    g_nmT[b][cls] = sqrtf(nm2T);
}

// ---------------------------------------------------------------------------
// Pass 3: streaming — no per-thread channel array. Dots are linear in raw v,
// so normalize after the dot. 4 pixels/thread, float4 loads.
// ---------------------------------------------------------------------------
__global__ void __launch_bounds__(THREADS, 4)
pass3_kernel(const float* __restrict__ S,
             const float* __restrict__ T,
             const int* __restrict__ TW) {
    const int b    = blockIdx.y;
    const int tile = blockIdx.x;
    const int tid  = threadIdx.x;
    const int is32 = g_is32;

    __shared__ float smS[2][Cn], smT[2][Cn], snS[2], snT[2];
    if (tid < 32)       (&smS[0][0])[tid]      = (&g_meanS[b][0][0])[tid];
    else if (tid < 64)  (&smT[0][0])[tid - 32] = (&g_meanT[b][0][0])[tid - 32];
    else if (tid < 66)  snS[tid - 64] = g_nmS[b][tid - 64];
    else if (tid < 68)  snT[tid - 66] = g_nmT[b][tid - 66];
    __syncthreads();

    const float* Sb  = S + ((size_t)b << 20);
    const float* Tb  = T + ((size_t)b << 20);
    const int*   twb = TW + (is32 ? ((size_t)b << 16) : ((size_t)b << 17));

    const float nS0 = snS[0], nS1 = snS[1], nT0 = snT[0], nT1 = snT[1];

    float acc = 0.f;
#pragma unroll
    for (int it = 0; it < ITERS3; ++it) {
        const int p = tile * PIX_PER_BLOCK + it * (THREADS * 4) + tid * 4;

        int c0, c1, c2, c3;
        load_cls4(twb, p, is32, c0, c1, c2, c3);
        const float s0 = (c0 == 0) ? 1.f : -1.f;
        const float s1 = (c1 == 0) ? 1.f : -1.f;
        const float s2 = (c2 == 0) ? 1.f : -1.f;
        const float s3 = (c3 == 0) ? 1.f : -1.f;

        float pcS0, pcS1, pcS2, pcS3;
        // ---- S (streamed) ----
        {
            float n0 = 0.f, n1 = 0.f, n2 = 0.f, n3 = 0.f;
            float dA0 = 0.f, dB0 = 0.f, dA1 = 0.f, dB1 = 0.f;
            float dA2 = 0.f, dB2 = 0.f, dA3 = 0.f, dB3 = 0.f;
#pragma unroll
            for (int c = 0; c < Cn; c++) {
                const float4 v = *(const float4*)(Sb + ((size_t)c << 16) + p);
                const float mA = smS[0][c], mB = smS[1][c];
                n0 = fmaf(v.x, v.x, n0); n1 = fmaf(v.y, v.y, n1);
                n2 = fmaf(v.z, v.z, n2); n3 = fmaf(v.w, v.w, n3);
                dA0 = fmaf(v.x, mA, dA0); dB0 = fmaf(v.x, mB, dB0);
                dA1 = fmaf(v.y, mA, dA1); dB1 = fmaf(v.y, mB, dB1);
                dA2 = fmaf(v.z, mA, dA2); dB2 = fmaf(v.z, mB, dB2);
                dA3 = fmaf(v.w, mA, dA3); dB3 = fmaf(v.w, mB, dB3);
            }
            const float i0 = rsqrtf(fmaxf(n0, 1e-24f)), i1 = rsqrtf(fmaxf(n1, 1e-24f));
            const float i2 = rsqrtf(fmaxf(n2, 1e-24f)), i3 = rsqrtf(fmaxf(n3, 1e-24f));
            const float f0 = sqrtf(n0) * i0, f1 = sqrtf(n1) * i1;
            const float f2 = sqrtf(n2) * i2, f3 = sqrtf(n3) * i3;
            const float cd0 = (dA0 * i0) / fmaxf(f0 * nS0, 1e-8f) - (dB0 * i0) / fmaxf(f0 * nS1, 1e-8f);
            const float cd1 = (dA1 * i1) / fmaxf(f1 * nS0, 1e-8f) - (dB1 * i1) / fmaxf(f1 * nS1, 1e-8f);
            const float cd2 = (dA2 * i2) / fmaxf(f2 * nS0, 1e-8f) - (dB2 * i2) / fmaxf(f2 * nS1, 1e-8f);
            const float cd3 = (dA3 * i3) / fmaxf(f3 * nS0, 1e-8f) - (dB3 * i3) / fmaxf(f3 * nS1, 1e-8f);
            pcS0 = expf(s0 * cd0); pcS1 = expf(s1 * cd1);
            pcS2 = expf(s2 * cd2); pcS3 = expf(s3 * cd3);
        }
        // ---- T (streamed) ----
        {
            float n0 = 0.f, n1 = 0.f, n2 = 0.f, n3 = 0.f;
            float dA0 = 0.f, dB0 = 0.f, dA1 = 0.f, dB1 = 0.f;
            float dA2 = 0.f, dB2 = 0.f, dA3 = 0.f, dB3 = 0.f;
#pragma unroll
            for (int c = 0; c < Cn; c++) {
                const float4 v = *(const float4*)(Tb + ((size_t)c << 16) + p);
                const float mA = smT[0][c], mB = smT[1][c];
                n0 = fmaf(v.x, v.x, n0); n1 = fmaf(v.y, v.y, n1);
                n2 = fmaf(v.z, v.z, n2); n3 = fmaf(v.w, v.w, n3);
                dA0 = fmaf(v.x, mA, dA0); dB0 = fmaf(v.x, mB, dB0);
                dA1 = fmaf(v.y, mA, dA1); dB1 = fmaf(v.y, mB, dB1);
                dA2 = fmaf(v.z, mA, dA2); dB2 = fmaf(v.z, mB, dB2);
                dA3 = fmaf(v.w, mA, dA3); dB3 = fmaf(v.w, mB, dB3);
            }
            const float i0 = rsqrtf(fmaxf(n0, 1e-24f)), i1 = rsqrtf(fmaxf(n1, 1e-24f));
            const float i2 = rsqrtf(fmaxf(n2, 1e-24f)), i3 = rsqrtf(fmaxf(n3, 1e-24f));
            const float f0 = sqrtf(n0) * i0, f1 = sqrtf(n1) * i1;
            const float f2 = sqrtf(n2) * i2, f3 = sqrtf(n3) * i3;
            const float cd0 = (dA0 * i0) / fmaxf(f0 * nT0, 1e-8f) - (dB0 * i0) / fmaxf(f0 * nT1, 1e-8f);
            const float cd1 = (dA1 * i1) / fmaxf(f1 * nT0, 1e-8f) - (dB1 * i1) / fmaxf(f1 * nT1, 1e-8f);
            const float cd2 = (dA2 * i2) / fmaxf(f2 * nT0, 1e-8f) - (dB2 * i2) / fmaxf(f2 * nT1, 1e-8f);
            const float cd3 = (dA3 * i3) / fmaxf(f3 * nT0, 1e-8f) - (dB3 * i3) / fmaxf(f3 * nT1, 1e-8f);
            const float d0 = pcS0 - expf(s0 * cd0);
            const float d1 = pcS1 - expf(s1 * cd1);
            const float d2 = pcS2 - expf(s2 * cd2);
            const float d3 = pcS3 - expf(s3 * cd3);
            acc += (fmaf(d0, d0, d1 * d1)) + (fmaf(d2, d2, d3 * d3));
        }
    }

    __shared__ float smse[THREADS / 32];
    acc = wred(acc);
    const int lane = tid & 31, w = tid >> 5;
    if (lane == 0) smse[w] = acc;
    __syncthreads();
    if (tid == 0) {
        float s = 0.f;
#pragma unroll
        for (int ww = 0; ww < THREADS / 32; ww++) s += smse[ww];
        atomicAdd(&g_mse, (double)s);
    }
}

__global__ void writeout_kernel(float* out) {
    out[0] = (float)(g_mse * (1.0 / ((double)Bn * (double)HWn)));
}

extern "C" void kernel_launch(void* const* d_in, const int* in_sizes, int n_in,
                              void* d_out, int out_size) {
    const float* S  = (const float*)d_in[0];
    const float* T  = (const float*)d_in[1];
    const int*   TW = (const int*)d_in[2];
    float* out = (float*)d_out;

    zero_detect_kernel<<<1, THREADS>>>(TW);
    dim3 grid(TILES, Bn);
    pass1_kernel<<<grid, THREADS>>>(S, TW, 0, 16, 1);
    pass1_kernel<<<grid, THREADS>>>(T, TW, 32, 48, 0);
    finalize_kernel<<<1, 64>>>();
    pass3_kernel<<<grid, THREADS>>>(S, T, TW);
    writeout_kernel<<<1, 1>>>(out);
}